// round 3
// baseline (speedup 1.0000x reference)
#include <cuda_runtime.h>
#include <cuda_bf16.h>
#include <cstdint>

#define NB 64
#define NM 512
#define ND 2048
#define NK 32

// ---- scratch (device globals: allocation-free) ----
__device__ __align__(256) __nv_bfloat16 g_wb[NK * ND];  // bf16 W copy (tiny)
__device__ float g_nsq[NB * NK];                        // cross-pair nsq exchange
__device__ int   g_cnt[NB];                             // pair arrival counters

// ---- smem layout (bytes) ----
#define OFF_STG 0                         // [2][32][264] f32  = 67584
#define OFF_W   67584                     // [2][32][264] bf16 = 33792
#define OFF_XH  101376                    // [32][1032] bf16   = 66048
#define OFF_LOG 167424                    // [32][36] f32      = 4608
#define OFF_SA  172032                    // [32][40] bf16     = 2560
#define OFF_RN  174592                    // [32] f32
#define OFF_COL 174720                    // [32] f32
#define OFF_NSQ 174848                    // [32] f32
#define SMEM_TOT 175104

__device__ __forceinline__ void mma_bf16(float c[4],
    unsigned a0, unsigned a1, unsigned a2, unsigned a3,
    unsigned b0, unsigned b1) {
  asm volatile(
    "mma.sync.aligned.m16n8k16.row.col.f32.bf16.bf16.f32 "
    "{%0,%1,%2,%3}, {%4,%5,%6,%7}, {%8,%9}, {%0,%1,%2,%3};\n"
    : "+f"(c[0]), "+f"(c[1]), "+f"(c[2]), "+f"(c[3])
    : "r"(a0), "r"(a1), "r"(a2), "r"(a3), "r"(b0), "r"(b1));
}
__device__ __forceinline__ void cp16(void* dst, const void* src) {
  unsigned d = (unsigned)__cvta_generic_to_shared(dst);
  asm volatile("cp.async.cg.shared.global [%0], [%1], 16;\n" :: "r"(d), "l"(src));
}
__device__ __forceinline__ void cp_commit() { asm volatile("cp.async.commit_group;\n"); }
__device__ __forceinline__ void cp_wait1()  { asm volatile("cp.async.wait_group 1;\n"); }

// ================= KZ: zero accumulators + convert W to bf16 =============
__global__ void kz_kernel(const float* __restrict__ Wm) {
  int blk = blockIdx.x, tid = threadIdx.x;
  if (blk < 32) {
    // W convert: 34 blocks? blocks 0..31 convert 65536 elems, 8 per thread
    int base = (blk * 256 + tid) * 8;
    float4 v0 = *reinterpret_cast<const float4*>(Wm + base);
    float4 v1 = *reinterpret_cast<const float4*>(Wm + base + 4);
    __nv_bfloat162 h0 = __float22bfloat162_rn(make_float2(v0.x, v0.y));
    __nv_bfloat162 h1 = __float22bfloat162_rn(make_float2(v0.z, v0.w));
    __nv_bfloat162 h2 = __float22bfloat162_rn(make_float2(v1.x, v1.y));
    __nv_bfloat162 h3 = __float22bfloat162_rn(make_float2(v1.z, v1.w));
    uint4 pk;
    pk.x = *reinterpret_cast<unsigned*>(&h0); pk.y = *reinterpret_cast<unsigned*>(&h1);
    pk.z = *reinterpret_cast<unsigned*>(&h2); pk.w = *reinterpret_cast<unsigned*>(&h3);
    *reinterpret_cast<uint4*>(g_wb + base) = pk;
  } else if (blk == 32) {
    // zero nsq (2048) and counters (64)
    for (int i = tid; i < NB * NK; i += 256) g_nsq[i] = 0.f;
    if (tid < NB) g_cnt[tid] = 0;
  }
}

// ================= fused kernel: one block per (batch, d-half) ============
__global__ __launch_bounds__(256) void fused_kernel(const float* __restrict__ x,
                                                    const float* __restrict__ cent,
                                                    float* __restrict__ out) {
  extern __shared__ __align__(16) char sm[];
  float* stg = reinterpret_cast<float*>(sm + OFF_STG);                 // [2][32][264]
  __nv_bfloat16* wch = reinterpret_cast<__nv_bfloat16*>(sm + OFF_W);   // [2][32][264]
  __nv_bfloat16* xh = reinterpret_cast<__nv_bfloat16*>(sm + OFF_XH);   // [32][1032]
  float (*slog)[36] = reinterpret_cast<float(*)[36]>(sm + OFF_LOG);    // [32][36]
  __nv_bfloat16 (*sA)[40] = reinterpret_cast<__nv_bfloat16(*)[40]>(sm + OFF_SA);
  float* srn  = reinterpret_cast<float*>(sm + OFF_RN);
  float* scol = reinterpret_cast<float*>(sm + OFF_COL);
  float* snsq = reinterpret_cast<float*>(sm + OFF_NSQ);

  const int tid = threadIdx.x, lane = tid & 31, w = tid >> 5;
  const int g = lane >> 2, q = lane & 3;
  const int b = blockIdx.x >> 1, h = blockIdx.x & 1;
  const float* xb = x + (size_t)b * NM * ND;

  // GEMM1 (logits): warp w -> mtile (w&1), n-row-base (w>>1)*8
  const int mt1 = w & 1, n1 = (w >> 1) * 8;
  // GEMM2 (vlad): warp w -> cluster-tile (w&1), d-range (w>>1)*256
  const int mt2 = w & 1, d2 = (w >> 1) * 256;
  // convert assignment: row tid>>3, col lanes tid&7 (stride-32 float4s)
  const int crow = tid >> 3, clane = tid & 7;

  if (tid < NK) { scol[tid] = 0.f; snsq[tid] = 0.f; }

  float c2[32][4];   // vlad accumulators: 128 regs
#pragma unroll
  for (int i = 0; i < 32; i++) { c2[i][0]=c2[i][1]=c2[i][2]=c2[i][3]=0.f; }
  float c1[4] = {0.f, 0.f, 0.f, 0.f};
  float ssq = 0.f;

  // chunk issuer: global chunk gc in [0,128): tile gc>>3, chunk col (gc&7)*256
  auto issue_chunk = [&](int gc) {
    const int m0 = (gc >> 3) * 32, col0 = (gc & 7) * 256;
    float* sdst = stg + (gc & 1) * (32 * 264);
    __nv_bfloat16* wdst = wch + (gc & 1) * (32 * 264);
#pragma unroll
    for (int j = 0; j < 8; j++) {        // x: 32 rows x 64 cp16 per row
      int op = tid + 256 * j;
      int row = op >> 6, sc = (op & 63) * 4;
      cp16(sdst + row * 264 + sc, xb + (size_t)(m0 + row) * ND + col0 + sc);
    }
#pragma unroll
    for (int j = 0; j < 4; j++) {        // W: 32 rows x 32 cp16 per row
      int op = tid + 256 * j;
      int row = op >> 5, sc = (op & 31) * 8;
      cp16(wdst + row * 264 + sc, g_wb + row * ND + col0 + sc);
    }
  };

  issue_chunk(0);
  cp_commit();
  __syncthreads();

  for (int t = 0; t < 16; t++) {
    // ================= phase A: stream + logits ====================
    for (int cc = 0; cc < 8; cc++) {
      const int gc = t * 8 + cc;
      if (gc + 1 < 128) issue_chunk(gc + 1);
      cp_commit();
      cp_wait1();
      __syncthreads();

      const float* scf = stg + (gc & 1) * (32 * 264);
      const __nv_bfloat16* wcf = wch + (gc & 1) * (32 * 264);
      const bool own = ((cc >> 2) == h);

      // convert + sumsq (+ xhalf store if own half)
      {
        const float* src = scf + crow * 264 + clane * 4;
        __nv_bfloat16* dst = xh + crow * 1032 + (cc & 3) * 256 + clane * 4;
#pragma unroll
        for (int i = 0; i < 8; i++) {
          float4 v = *reinterpret_cast<const float4*>(src + 32 * i);
          ssq += v.x*v.x + v.y*v.y + v.z*v.z + v.w*v.w;
          if (own) {
            __nv_bfloat162 p0 = __float22bfloat162_rn(make_float2(v.x, v.y));
            __nv_bfloat162 p1 = __float22bfloat162_rn(make_float2(v.z, v.w));
            uint2 pk;
            pk.x = *reinterpret_cast<unsigned*>(&p0);
            pk.y = *reinterpret_cast<unsigned*>(&p1);
            *reinterpret_cast<uint2*>(dst + 32 * i) = pk;
          }
        }
      }

      // logits mma over chunk: 16 k-steps of 16
      {
        const int rl = 16 * mt1 + g;
#pragma unroll
        for (int ks = 0; ks < 16; ks++) {
          const int k0 = ks * 16;
          float2 pa = *reinterpret_cast<const float2*>(scf + rl * 264 + k0 + 2*q);
          float2 pb = *reinterpret_cast<const float2*>(scf + (rl+8) * 264 + k0 + 2*q);
          float2 pc = *reinterpret_cast<const float2*>(scf + rl * 264 + k0 + 2*q + 8);
          float2 pd = *reinterpret_cast<const float2*>(scf + (rl+8) * 264 + k0 + 2*q + 8);
          __nv_bfloat162 ha = __float22bfloat162_rn(pa);
          __nv_bfloat162 hb = __float22bfloat162_rn(pb);
          __nv_bfloat162 hc = __float22bfloat162_rn(pc);
          __nv_bfloat162 hd = __float22bfloat162_rn(pd);
          unsigned b0 = *reinterpret_cast<const unsigned*>(wcf + (n1 + g) * 264 + k0 + 2*q);
          unsigned b1 = *reinterpret_cast<const unsigned*>(wcf + (n1 + g) * 264 + k0 + 2*q + 8);
          mma_bf16(c1,
                   *reinterpret_cast<unsigned*>(&ha), *reinterpret_cast<unsigned*>(&hb),
                   *reinterpret_cast<unsigned*>(&hc), *reinterpret_cast<unsigned*>(&hd),
                   b0, b1);
        }
      }
      __syncthreads();
    }

    // ================= phase B: softmax + sa' + colsum ==============
    // row sumsq: 8 threads per row -> reduce over lane bits 0..2
    {
      float v = ssq;
      v += __shfl_xor_sync(0xffffffffu, v, 1);
      v += __shfl_xor_sync(0xffffffffu, v, 2);
      v += __shfl_xor_sync(0xffffffffu, v, 4);
      if ((lane & 7) == 0) srn[crow] = v;
      ssq = 0.f;
    }
    // dump logits frags
    {
      const int rl = 16 * mt1 + g;
      slog[rl    ][n1 + 2*q]     = c1[0];
      slog[rl    ][n1 + 2*q + 1] = c1[1];
      slog[rl + 8][n1 + 2*q]     = c1[2];
      slog[rl + 8][n1 + 2*q + 1] = c1[3];
      c1[0] = c1[1] = c1[2] = c1[3] = 0.f;
    }
    __syncthreads();

    if (tid < 32) {
      float rn = rsqrtf(fmaxf(srn[tid], 1e-24f));
      float l[NK];
      float mx = -1e30f;
#pragma unroll
      for (int k = 0; k < NK; k++) { l[k] = slog[tid][k] * rn; mx = fmaxf(mx, l[k]); }
      float s = 0.f;
#pragma unroll
      for (int k = 0; k < NK; k++) { l[k] = expf(l[k] - mx); s += l[k]; }
      float inv = 1.f / s;
#pragma unroll
      for (int k = 0; k < NK; k++) {
        float sa = l[k] * inv;
        slog[tid][k] = sa;                       // for colsum
        sA[k][tid] = __float2bfloat16(sa * rn);  // transposed sa'
      }
    }
    __syncthreads();
    if (tid < 32) {   // colsum: thread k sums column k over 32 rows
      float s = 0.f;
#pragma unroll
      for (int m = 0; m < 32; m++) s += slog[m][tid];
      scol[tid] += s;
    }

    // ================= phase C: vlad GEMM accumulate ================
    {
      const int rl = 16 * mt2 + g;
#pragma unroll
      for (int ks = 0; ks < 2; ks++) {
        const int k0 = ks * 16;
        unsigned a0 = *reinterpret_cast<const unsigned*>(&sA[rl    ][k0 + 2*q]);
        unsigned a1 = *reinterpret_cast<const unsigned*>(&sA[rl + 8][k0 + 2*q]);
        unsigned a2 = *reinterpret_cast<const unsigned*>(&sA[rl    ][k0 + 2*q + 8]);
        unsigned a3 = *reinterpret_cast<const unsigned*>(&sA[rl + 8][k0 + 2*q + 8]);
#pragma unroll
        for (int nt = 0; nt < 32; nt++) {
          unsigned b0, b1;
          unsigned addr = (unsigned)__cvta_generic_to_shared(
              xh + (k0 + (lane & 15)) * 1032 + d2 + nt * 8);
          asm volatile(
              "ldmatrix.sync.aligned.m8n8.x2.trans.shared.b16 {%0,%1}, [%2];\n"
              : "=r"(b0), "=r"(b1) : "r"(addr));
          mma_bf16(c2[nt], a0, a1, a2, a3, b0, b1);
        }
      }
    }
    __syncthreads();
  }

  // ================= epilogue =====================================
  const int rl = 16 * mt2 + g, rh = rl + 8;
  const float Sl = scol[rl], Sh = scol[rh];
  float sql = 0.f, sqh = 0.f;
#pragma unroll
  for (int nt = 0; nt < 32; nt++) {
    const int gcol = h * 1024 + d2 + nt * 8 + 2 * q;
    float2 cl = *reinterpret_cast<const float2*>(cent + (size_t)rl * ND + gcol);
    float2 ch = *reinterpret_cast<const float2*>(cent + (size_t)rh * ND + gcol);
    c2[nt][0] -= Sl * cl.x;  c2[nt][1] -= Sl * cl.y;
    c2[nt][2] -= Sh * ch.x;  c2[nt][3] -= Sh * ch.y;
    sql += c2[nt][0]*c2[nt][0] + c2[nt][1]*c2[nt][1];
    sqh += c2[nt][2]*c2[nt][2] + c2[nt][3]*c2[nt][3];
  }
  sql += __shfl_xor_sync(0xffffffffu, sql, 1);
  sql += __shfl_xor_sync(0xffffffffu, sql, 2);
  sqh += __shfl_xor_sync(0xffffffffu, sqh, 1);
  sqh += __shfl_xor_sync(0xffffffffu, sqh, 2);
  if (q == 0) { atomicAdd(&snsq[rl], sql); atomicAdd(&snsq[rh], sqh); }
  __syncthreads();

  // cross-pair nsq exchange (2 blocks per batch, single wave -> safe spin)
  if (tid < 32) atomicAdd(&g_nsq[b * NK + tid], snsq[tid]);
  __threadfence();
  __syncthreads();
  if (tid == 0) {
    atomicAdd(&g_cnt[b], 1);
    while (*reinterpret_cast<volatile int*>(&g_cnt[b]) < 2) { }
  }
  __syncthreads();
  __threadfence();
  if (tid < 32) {
    float tot = atomicAdd(&g_nsq[b * NK + tid], 0.0f);
    srn[tid] = rsqrtf(fmaxf(tot, 1e-24f) * 32.0f);  // includes final sqrt(K)
  }
  __syncthreads();

  const float scl = srn[rl], sch = srn[rh];
  float* ob = out + (size_t)b * (NK * ND) + h * 1024;
#pragma unroll
  for (int nt = 0; nt < 32; nt++) {
    const int dcol = d2 + nt * 8 + 2 * q;
    float2 o0; o0.x = c2[nt][0] * scl; o0.y = c2[nt][1] * scl;
    float2 o1; o1.x = c2[nt][2] * sch; o1.y = c2[nt][3] * sch;
    *reinterpret_cast<float2*>(ob + (size_t)rl * ND + dcol) = o0;
    *reinterpret_cast<float2*>(ob + (size_t)rh * ND + dcol) = o1;
  }
}

extern "C" void kernel_launch(void* const* d_in, const int* in_sizes, int n_in,
                              void* d_out, int out_size) {
  const float* x    = (const float*)d_in[0];
  const float* Wm   = (const float*)d_in[1];
  const float* cent = (const float*)d_in[2];
  float* out = (float*)d_out;

  static bool attr_set = false;
  if (!attr_set) {
    cudaFuncSetAttribute(fused_kernel,
                         cudaFuncAttributeMaxDynamicSharedMemorySize, SMEM_TOT);
    attr_set = true;
  }

  kz_kernel<<<33, 256>>>(Wm);
  fused_kernel<<<NB * 2, 256, SMEM_TOT>>>(x, cent, out);
}

// round 4
// speedup vs baseline: 1.6939x; 1.6939x over previous
#include <cuda_runtime.h>
#include <cuda_bf16.h>
#include <cstdint>

#define NB 64
#define NM 512
#define ND 2048
#define NK 32

// ---- scratch (device globals: allocation-free) ----
__device__ __align__(256) __nv_bfloat16 g_xraw[(size_t)NB*NM*ND];  // bf16 x copy
__device__ __align__(256) __nv_bfloat16 g_sap[NB*NM*NK];           // sa * rnorm
__device__ __align__(256) __nv_bfloat16 g_wb[NK*ND];               // bf16 W
__device__ float g_S[NB*NK];
__device__ float g_nsq[NB*NK];
__device__ __align__(256) float g_vlad[NB*NK*ND];

__device__ __forceinline__ void mma_bf16(float c[4],
    unsigned a0, unsigned a1, unsigned a2, unsigned a3,
    unsigned b0, unsigned b1) {
  asm volatile(
    "mma.sync.aligned.m16n8k16.row.col.f32.bf16.bf16.f32 "
    "{%0,%1,%2,%3}, {%4,%5,%6,%7}, {%8,%9}, {%0,%1,%2,%3};\n"
    : "+f"(c[0]), "+f"(c[1]), "+f"(c[2]), "+f"(c[3])
    : "r"(a0), "r"(a1), "r"(a2), "r"(a3), "r"(b0), "r"(b1));
}
__device__ __forceinline__ void cp16(void* dst, const void* src) {
  unsigned d = (unsigned)__cvta_generic_to_shared(dst);
  asm volatile("cp.async.cg.shared.global [%0], [%1], 16;\n" :: "r"(d), "l"(src));
}
__device__ __forceinline__ void cp_commit() { asm volatile("cp.async.commit_group;\n"); }
__device__ __forceinline__ void cp_wait1()  { asm volatile("cp.async.wait_group 1;\n"); }

// ================= KZ: zero accumulators + convert W =================
__global__ void kz_kernel(const float* __restrict__ Wm) {
  int blk = blockIdx.x, tid = threadIdx.x;
  if (blk < 32) {
    int base = (blk * 256 + tid) * 8;   // 32*256*8 = 65536 = NK*ND
    float4 v0 = *reinterpret_cast<const float4*>(Wm + base);
    float4 v1 = *reinterpret_cast<const float4*>(Wm + base + 4);
    __nv_bfloat162 h0 = __float22bfloat162_rn(make_float2(v0.x, v0.y));
    __nv_bfloat162 h1 = __float22bfloat162_rn(make_float2(v0.z, v0.w));
    __nv_bfloat162 h2 = __float22bfloat162_rn(make_float2(v1.x, v1.y));
    __nv_bfloat162 h3 = __float22bfloat162_rn(make_float2(v1.z, v1.w));
    uint4 pk;
    pk.x = *reinterpret_cast<unsigned*>(&h0); pk.y = *reinterpret_cast<unsigned*>(&h1);
    pk.z = *reinterpret_cast<unsigned*>(&h2); pk.w = *reinterpret_cast<unsigned*>(&h3);
    *reinterpret_cast<uint4*>(g_wb + base) = pk;
  } else {
    for (int i = tid; i < NB * NK; i += 256) { g_S[i] = 0.f; g_nsq[i] = 0.f; }
  }
}

// ================= KA: norm + logits + softmax ==========================
// 64 rows/block, 256 threads, chunk=128 cols, 16 iters, double-buffered.
#define KA_FS 132                      // fp32 staging stride (floats)
#define KA_HS 136                      // bf16 tile stride (halves)
#define OFF_STG 0                      // [2][64][132] f32  = 67584
#define OFF_XSB 67584                  // [64][136] bf16    = 17408
#define OFF_WSB 84992                  // [2][32][136] bf16 = 17408
#define KA_SMEM 102400
__global__ __launch_bounds__(256) void ka_kernel(const float* __restrict__ x) {
  extern __shared__ __align__(16) char kab[];
  float* stg = reinterpret_cast<float*>(kab + OFF_STG);
  __nv_bfloat16* xsb = reinterpret_cast<__nv_bfloat16*>(kab + OFF_XSB);
  __nv_bfloat16* wsb = reinterpret_cast<__nv_bfloat16*>(kab + OFF_WSB);
  float (*slog)[36] = reinterpret_cast<float(*)[36]>(kab);   // alias (post-loop)
  __shared__ float srn[64];

  const int tid = threadIdx.x, lane = tid & 31, w = tid >> 5;
  const int g = lane >> 2, q = lane & 3;
  const int r0 = blockIdx.x * 64;
  const int mt = w & 3, nbase = (w >> 2) * 16;
  const int crow = tid >> 2, cj = tid & 3;   // convert: 4 threads per row

  float c[2][4];
#pragma unroll
  for (int i = 0; i < 2; i++) { c[i][0]=c[i][1]=c[i][2]=c[i][3]=0.f; }
  float ssq = 0.f;

  auto issue_chunk = [&](int ch) {
    float* sdst = stg + (ch & 1) * (64 * KA_FS);
    __nv_bfloat16* wdst = wsb + (ch & 1) * (32 * KA_HS);
    const int col0 = ch * 128;
#pragma unroll
    for (int j = 0; j < 8; j++) {      // x: 64 rows x 32 cp16
      int op = tid + 256 * j;
      int row = op >> 5, seg = (op & 31) * 4;
      cp16(sdst + row * KA_FS + seg, x + (size_t)(r0 + row) * ND + col0 + seg);
    }
#pragma unroll
    for (int j = 0; j < 2; j++) {      // W: 32 rows x 16 cp16
      int op = tid + 256 * j;
      int row = op >> 4, seg = (op & 15) * 8;
      cp16(wdst + row * KA_HS + seg, g_wb + row * ND + col0 + seg);
    }
  };

  issue_chunk(0);
  cp_commit();

  // ldmatrix A-fragment address (constant across iters except k0)
  const int lm = lane >> 3;
  const int arow = 16 * mt + (lm & 1) * 8 + (lane & 7);
  const int acol = (lm >> 1) * 8;

  for (int it = 0; it < 16; it++) {
    if (it + 1 < 16) issue_chunk(it + 1);
    cp_commit();
    cp_wait1();
    __syncthreads();

    const float* sf = stg + (it & 1) * (64 * KA_FS);
    const __nv_bfloat16* wb = wsb + (it & 1) * (32 * KA_HS);

    // convert fp32 -> bf16 (smem tile + global), accumulate sumsq
    {
      const float* src = sf + crow * KA_FS + cj * 8;
      __nv_bfloat16* sdst = xsb + crow * KA_HS + cj * 8;
      __nv_bfloat16* gdst = g_xraw + (size_t)(r0 + crow) * ND + it * 128 + cj * 8;
#pragma unroll
      for (int i = 0; i < 4; i++) {
        float4 a = *reinterpret_cast<const float4*>(src + 32 * i);
        float4 bb = *reinterpret_cast<const float4*>(src + 32 * i + 4);
        ssq += a.x*a.x + a.y*a.y + a.z*a.z + a.w*a.w
             + bb.x*bb.x + bb.y*bb.y + bb.z*bb.z + bb.w*bb.w;
        __nv_bfloat162 p0 = __float22bfloat162_rn(make_float2(a.x, a.y));
        __nv_bfloat162 p1 = __float22bfloat162_rn(make_float2(a.z, a.w));
        __nv_bfloat162 p2 = __float22bfloat162_rn(make_float2(bb.x, bb.y));
        __nv_bfloat162 p3 = __float22bfloat162_rn(make_float2(bb.z, bb.w));
        uint4 pk;
        pk.x = *reinterpret_cast<unsigned*>(&p0); pk.y = *reinterpret_cast<unsigned*>(&p1);
        pk.z = *reinterpret_cast<unsigned*>(&p2); pk.w = *reinterpret_cast<unsigned*>(&p3);
        *reinterpret_cast<uint4*>(sdst + 32 * i) = pk;
        *reinterpret_cast<uint4*>(gdst + 32 * i) = pk;
      }
    }
    __syncthreads();

    // logits mma: 8 k-steps of 16; A via ldmatrix.x4, B via LDS.32
#pragma unroll
    for (int ks = 0; ks < 8; ks++) {
      const int k0 = ks * 16;
      unsigned a0, a1, a2, a3;
      unsigned addr = (unsigned)__cvta_generic_to_shared(
          xsb + arow * KA_HS + k0 + acol);
      asm volatile(
          "ldmatrix.sync.aligned.m8n8.x4.shared.b16 {%0,%1,%2,%3}, [%4];\n"
          : "=r"(a0), "=r"(a1), "=r"(a2), "=r"(a3) : "r"(addr));
#pragma unroll
      for (int nt = 0; nt < 2; nt++) {
        unsigned b0 = *reinterpret_cast<const unsigned*>(
            wb + (nbase + 8*nt + g) * KA_HS + k0 + 2*q);
        unsigned b1 = *reinterpret_cast<const unsigned*>(
            wb + (nbase + 8*nt + g) * KA_HS + k0 + 2*q + 8);
        mma_bf16(c[nt], a0, a1, a2, a3, b0, b1);
      }
    }
  }

  // row norms: 4 threads per row
  ssq += __shfl_xor_sync(0xffffffffu, ssq, 1);
  ssq += __shfl_xor_sync(0xffffffffu, ssq, 2);
  if (cj == 0) srn[crow] = rsqrtf(fmaxf(ssq, 1e-24f));

  // dump logits (slog aliases stg; loop done, regions distinct from xsb/wsb)
#pragma unroll
  for (int nt = 0; nt < 2; nt++) {
    slog[16*mt + g    ][nbase + 8*nt + 2*q]     = c[nt][0];
    slog[16*mt + g    ][nbase + 8*nt + 2*q + 1] = c[nt][1];
    slog[16*mt + g + 8][nbase + 8*nt + 2*q]     = c[nt][2];
    slog[16*mt + g + 8][nbase + 8*nt + 2*q + 1] = c[nt][3];
  }
  __syncthreads();

  // softmax (one thread per row), write sa' bf16, leave sa fp32 in slog
  if (tid < 64) {
    float rn = srn[tid];
    float l[NK];
    float mx = -1e30f;
#pragma unroll
    for (int k = 0; k < NK; k++) { l[k] = slog[tid][k] * rn; mx = fmaxf(mx, l[k]); }
    float s = 0.f;
#pragma unroll
    for (int k = 0; k < NK; k++) { l[k] = expf(l[k] - mx); s += l[k]; }
    float inv = 1.f / s;
#pragma unroll
    for (int k = 0; k < NK; k++) l[k] *= inv;
#pragma unroll
    for (int k = 0; k < NK; k += 8) {
      __nv_bfloat162 q0 = __float22bfloat162_rn(make_float2(l[k]*rn,   l[k+1]*rn));
      __nv_bfloat162 q1 = __float22bfloat162_rn(make_float2(l[k+2]*rn, l[k+3]*rn));
      __nv_bfloat162 q2 = __float22bfloat162_rn(make_float2(l[k+4]*rn, l[k+5]*rn));
      __nv_bfloat162 q3 = __float22bfloat162_rn(make_float2(l[k+6]*rn, l[k+7]*rn));
      uint4 pk;
      pk.x = *reinterpret_cast<unsigned*>(&q0); pk.y = *reinterpret_cast<unsigned*>(&q1);
      pk.z = *reinterpret_cast<unsigned*>(&q2); pk.w = *reinterpret_cast<unsigned*>(&q3);
      *reinterpret_cast<uint4*>(&g_sap[(size_t)(r0 + tid) * NK + k]) = pk;
    }
#pragma unroll
    for (int k = 0; k < NK; k++) slog[tid][k] = l[k];
  }
  __syncthreads();

  if (tid < NK) {
    float s = 0.f;
#pragma unroll
    for (int r = 0; r < 64; r++) s += slog[r][tid];
    atomicAdd(&g_S[(r0 / NM) * NK + tid], s);
  }
}

// ================= KB: agg GEMM, MC=64 per stage, 8 stages ==============
#define KB_SBS 264   // x tile stride (halves), 33 16B-units (odd)
#define KB_SAS 72    // sa'^T tile stride (halves)
#define OFFB_SB 0                       // [2][64][264] bf16 = 67584
#define OFFB_SA 67584                   // [2][32][72] bf16  = 9216
#define KB_SMEM 76800
__global__ __launch_bounds__(256) void kb_kernel(const float* __restrict__ cent) {
  extern __shared__ __align__(16) char kbb[];
  __nv_bfloat16* sB = reinterpret_cast<__nv_bfloat16*>(kbb + OFFB_SB);
  __nv_bfloat16* sA = reinterpret_cast<__nv_bfloat16*>(kbb + OFFB_SA);
  __shared__ float sS[NK];

  const int tid = threadIdx.x, lane = tid & 31, w = tid >> 5;
  const int g = lane >> 2, q = lane & 3;
  const int b  = blockIdx.x >> 3;
  const int d0 = (blockIdx.x & 7) * 256;
  if (tid < NK) sS[tid] = g_S[b * NK + tid];

  const int mt = w & 1, nbase = (w >> 1) * 64;
  const int arow = tid >> 2, aseg = tid & 3;   // sa': 64 rows x 4 uint4-segs
  float c[8][4];
#pragma unroll
  for (int i = 0; i < 8; i++) { c[i][0]=c[i][1]=c[i][2]=c[i][3]=0.f; }

  const __nv_bfloat16* xb = g_xraw + (size_t)b * NM * ND + d0;
  const __nv_bfloat16* ab = g_sap + (size_t)b * NM * NK;

  // prologue: stage 0
  {
#pragma unroll
    for (int j = 0; j < 8; j++) {
      int op = tid + 256 * j;
      int row = op >> 5, seg = (op & 31) * 8;
      cp16(sB + row * KB_SBS + seg, xb + (size_t)row * ND + seg);
    }
    cp_commit();
    uint4 pk = *reinterpret_cast<const uint4*>(ab + arow * NK + aseg * 8);
    const __nv_bfloat16* hp = reinterpret_cast<const __nv_bfloat16*>(&pk);
#pragma unroll
    for (int jj = 0; jj < 8; jj++) sA[(aseg * 8 + jj) * KB_SAS + arow] = hp[jj];
  }

  for (int it = 0; it < 8; it++) {
    const int buf = it & 1, nbuf = buf ^ 1;
    const bool more = (it + 1 < 8);
    uint4 pk;
    if (more) {
      const int m0 = (it + 1) * 64;
#pragma unroll
      for (int j = 0; j < 8; j++) {
        int op = tid + 256 * j;
        int row = op >> 5, seg = (op & 31) * 8;
        cp16(sB + nbuf * (64 * KB_SBS) + row * KB_SBS + seg,
             xb + (size_t)(m0 + row) * ND + seg);
      }
      pk = *reinterpret_cast<const uint4*>(ab + (m0 + arow) * NK + aseg * 8);
    }
    cp_commit();
    cp_wait1();
    __syncthreads();

    const __nv_bfloat16* sBb = sB + buf * (64 * KB_SBS);
    const __nv_bfloat16* sAb = sA + buf * (32 * KB_SAS);
#pragma unroll
    for (int ks = 0; ks < 4; ks++) {
      const int k0 = ks * 16;
      unsigned a0 = *reinterpret_cast<const unsigned*>(sAb + (16*mt + g    ) * KB_SAS + k0 + 2*q);
      unsigned a1 = *reinterpret_cast<const unsigned*>(sAb + (16*mt + g + 8) * KB_SAS + k0 + 2*q);
      unsigned a2 = *reinterpret_cast<const unsigned*>(sAb + (16*mt + g    ) * KB_SAS + k0 + 2*q + 8);
      unsigned a3 = *reinterpret_cast<const unsigned*>(sAb + (16*mt + g + 8) * KB_SAS + k0 + 2*q + 8);
#pragma unroll
      for (int nt = 0; nt < 8; nt++) {
        unsigned b0, b1;
        unsigned addr = (unsigned)__cvta_generic_to_shared(
            sBb + (k0 + (lane & 15)) * KB_SBS + nbase + 8 * nt);
        asm volatile(
            "ldmatrix.sync.aligned.m8n8.x2.trans.shared.b16 {%0,%1}, [%2];\n"
            : "=r"(b0), "=r"(b1) : "r"(addr));
        mma_bf16(c[nt], a0, a1, a2, a3, b0, b1);
      }
    }

    if (more) {
      const __nv_bfloat16* hp = reinterpret_cast<const __nv_bfloat16*>(&pk);
#pragma unroll
      for (int jj = 0; jj < 8; jj++)
        sA[nbuf * (32 * KB_SAS) + (aseg * 8 + jj) * KB_SAS + arow] = hp[jj];
    }
    __syncthreads();
  }

  // epilogue: vlad = C - S_k * centroid ; per-(b,k) sumsq ; store vlad
  const int rl = 16 * mt + g, rh = rl + 8;
  const float Sl = sS[rl], Sh = sS[rh];
  float sql = 0.f, sqh = 0.f;
#pragma unroll
  for (int nt = 0; nt < 8; nt++) {
    int col = d0 + nbase + 8 * nt + 2 * q;
    float2 cl = *reinterpret_cast<const float2*>(cent + (size_t)rl * ND + col);
    float2 ch = *reinterpret_cast<const float2*>(cent + (size_t)rh * ND + col);
    float v0 = c[nt][0] - Sl * cl.x, v1 = c[nt][1] - Sl * cl.y;
    float v2 = c[nt][2] - Sh * ch.x, v3 = c[nt][3] - Sh * ch.y;
    sql += v0 * v0 + v1 * v1;
    sqh += v2 * v2 + v3 * v3;
    float2 o0; o0.x = v0; o0.y = v1;
    float2 o1; o1.x = v2; o1.y = v3;
    *reinterpret_cast<float2*>(&g_vlad[(size_t)(b * NK + rl) * ND + col]) = o0;
    *reinterpret_cast<float2*>(&g_vlad[(size_t)(b * NK + rh) * ND + col]) = o1;
  }
  sql += __shfl_xor_sync(0xffffffffu, sql, 1);
  sql += __shfl_xor_sync(0xffffffffu, sql, 2);
  sqh += __shfl_xor_sync(0xffffffffu, sqh, 1);
  sqh += __shfl_xor_sync(0xffffffffu, sqh, 2);
  if (q == 0) {
    atomicAdd(&g_nsq[b * NK + rl], sql);
    atomicAdd(&g_nsq[b * NK + rh], sqh);
  }
}

// ================= KC: final scaling ====================================
__global__ __launch_bounds__(256) void kc_kernel(float* __restrict__ out) {
  int t = blockIdx.x * 256 + threadIdx.x;
  int e = t * 8;
  int row = e >> 11;  // b*K + k
  float sc = rsqrtf(fmaxf(g_nsq[row], 1e-24f) * 32.0f);
  float4 v0 = *reinterpret_cast<float4*>(&g_vlad[e]);
  float4 v1 = *reinterpret_cast<float4*>(&g_vlad[e + 4]);
  v0.x *= sc; v0.y *= sc; v0.z *= sc; v0.w *= sc;
  v1.x *= sc; v1.y *= sc; v1.z *= sc; v1.w *= sc;
  *reinterpret_cast<float4*>(out + e)     = v0;
  *reinterpret_cast<float4*>(out + e + 4) = v1;
}

extern "C" void kernel_launch(void* const* d_in, const int* in_sizes, int n_in,
                              void* d_out, int out_size) {
  const float* x    = (const float*)d_in[0];
  const float* Wm   = (const float*)d_in[1];
  const float* cent = (const float*)d_in[2];
  float* out = (float*)d_out;

  static bool attr_set = false;
  if (!attr_set) {
    cudaFuncSetAttribute(ka_kernel,
                         cudaFuncAttributeMaxDynamicSharedMemorySize, KA_SMEM);
    cudaFuncSetAttribute(kb_kernel,
                         cudaFuncAttributeMaxDynamicSharedMemorySize, KB_SMEM);
    attr_set = true;
  }

  kz_kernel<<<33, 256>>>(Wm);
  ka_kernel<<<(NB * NM) / 64, 256, KA_SMEM>>>(x);
  kb_kernel<<<NB * 8, 256, KB_SMEM>>>(cent);
  kc_kernel<<<(NB * NK * ND) / (256 * 8), 256>>>(out);
}